// round 1
// baseline (speedup 1.0000x reference)
#include <cuda_runtime.h>
#include <cstdint>

#define CH 16  // K-chunk for weight staging

__device__ float g_wqsum[128];

// Precompute column sums of Wq: wqsum[c] = sum_o Wq[o*128 + c]
__global__ void wqsum_kernel(const float* __restrict__ Wq) {
    int c = threadIdx.x;
    float s0 = 0.f, s1 = 0.f, s2 = 0.f, s3 = 0.f;
    #pragma unroll
    for (int o = 0; o < 128; o += 4) {
        s0 += Wq[(o + 0) * 128 + c];
        s1 += Wq[(o + 1) * 128 + c];
        s2 += Wq[(o + 2) * 128 + c];
        s3 += Wq[(o + 3) * 128 + c];
    }
    g_wqsum[c] = (s0 + s1) + (s2 + s3);
}

__device__ __forceinline__ void fma2(unsigned long long& d, unsigned long long a,
                                     unsigned long long b) {
    asm("fma.rn.f32x2 %0, %1, %2, %0;" : "+l"(d) : "l"(a), "l"(b));
}
__device__ __forceinline__ unsigned long long dup2(float w) {
    unsigned long long r;
    asm("mov.b64 %0, {%1, %1};" : "=l"(r) : "f"(w));
    return r;
}

// acc[j_local][pair] over output tile rows j = ty*8..+7, cols n = tx*8..+7 (pairs).
// W is 128x128 row-major (out_ch x in_ch). sIn is [128 ch][128 n] tile in smem.
__device__ __forceinline__ void gemm_128(const float* __restrict__ W,
                                         const float* sIn, float* sW,
                                         unsigned long long acc[8][4],
                                         int tx, int ty, int tid) {
    #pragma unroll 1
    for (int kc0 = 0; kc0 < 128; kc0 += CH) {
        // Stage W chunk transposed: sW[kc][j] = W[j][kc0+kc]
        #pragma unroll
        for (int i = tid; i < 128 * (CH / 4); i += 256) {
            int j = i >> 2;
            int kg = i & 3;
            float4 w = __ldg((const float4*)(W + j * 128 + kc0 + kg * 4));
            sW[(kg * 4 + 0) * 128 + j] = w.x;
            sW[(kg * 4 + 1) * 128 + j] = w.y;
            sW[(kg * 4 + 2) * 128 + j] = w.z;
            sW[(kg * 4 + 3) * 128 + j] = w.w;
        }
        __syncthreads();
        #pragma unroll
        for (int kk = 0; kk < CH; kk++) {
            const unsigned long long* pr =
                (const unsigned long long*)(sIn + (kc0 + kk) * 128 + tx * 8);
            unsigned long long p0 = pr[0], p1 = pr[1], p2 = pr[2], p3 = pr[3];
            const float* wr = sW + kk * 128 + ty * 8;
            float wv[8];
            *(float4*)(wv) = *(const float4*)(wr);
            *(float4*)(wv + 4) = *(const float4*)(wr + 4);
            #pragma unroll
            for (int r = 0; r < 8; r++) {
                unsigned long long wp = dup2(wv[r]);
                fma2(acc[r][0], wp, p0);
                fma2(acc[r][1], wp, p1);
                fma2(acc[r][2], wp, p2);
                fma2(acc[r][3], wp, p3);
            }
        }
        __syncthreads();
    }
}

// smem layout (floats):
//   sP   [128][128]  pos tile           @ 0
//   sF   [128][128]  feat tile          @ 16384
//   sK   [128][128]  K result / exp(e)  @ 32768
//   sW   [CH][128]   weight chunk       @ 49152
//   s_sq [128]                          @ 49152 + CH*128
//   s_inv[128]                          @ +128
__global__ void __launch_bounds__(256, 1)
csa_kernel(const float* __restrict__ feat, const float* __restrict__ pos,
           const float* __restrict__ Wk, const float* __restrict__ Wv,
           float* __restrict__ out) {
    extern __shared__ float sm[];
    float* sP = sm;
    float* sF = sm + 16384;
    float* sK = sm + 32768;
    float* sW = sm + 49152;
    float* s_sq = sm + 49152 + CH * 128;
    float* s_inv = s_sq + 128;

    const int tid = threadIdx.x;
    const int tx = tid & 15;
    const int ty = tid >> 4;
    const size_t base = (size_t)blockIdx.y * (128u * 16384u) + (size_t)blockIdx.x * 128u;

    // Load pos/feat tiles: 128 rows x 128 cols each, via float4 (coalesced 512B rows)
    #pragma unroll
    for (int i = tid; i < 128 * 32; i += 256) {
        int r = i >> 5, c4 = i & 31;
        const float* gp = pos + base + (size_t)r * 16384;
        const float* gf = feat + base + (size_t)r * 16384;
        ((float4*)sP)[r * 32 + c4] = __ldg((const float4*)gp + c4);
        ((float4*)sF)[r * 32 + c4] = __ldg((const float4*)gf + c4);
    }
    __syncthreads();

    // sq[n] = sum_c wqsum[c] * pos[c,n]  (column reads: bank = n%32, conflict-free)
    if (tid < 128) {
        float a0 = 0.f, a1 = 0.f, a2 = 0.f, a3 = 0.f;
        #pragma unroll
        for (int c = 0; c < 128; c += 4) {
            a0 = fmaf(g_wqsum[c + 0], sP[(c + 0) * 128 + tid], a0);
            a1 = fmaf(g_wqsum[c + 1], sP[(c + 1) * 128 + tid], a1);
            a2 = fmaf(g_wqsum[c + 2], sP[(c + 2) * 128 + tid], a2);
            a3 = fmaf(g_wqsum[c + 3], sP[(c + 3) * 128 + tid], a3);
        }
        s_sq[tid] = (a0 + a1) + (a2 + a3);
    }
    // (GEMM syncthreads below orders s_sq before any consumer)

    unsigned long long acc[8][4];
    #pragma unroll
    for (int r = 0; r < 8; r++)
        #pragma unroll
        for (int c = 0; c < 4; c++) acc[r][c] = 0ull;

    // GEMM 1: K = Wk * pos_tile
    gemm_128(Wk, sP, sW, acc, tx, ty, tid);

    // Stash K tile into smem, reset accumulators
    #pragma unroll
    for (int r = 0; r < 8; r++) {
        unsigned long long* kr = (unsigned long long*)(sK + (ty * 8 + r) * 128 + tx * 8);
        #pragma unroll
        for (int c = 0; c < 4; c++) {
            kr[c] = acc[r][c];
            acc[r][c] = 0ull;
        }
    }

    // GEMM 2: V = Wv * feat_tile  (V stays in registers; ends with __syncthreads)
    gemm_128(Wv, sF, sW, acc, tx, ty, tid);

    // Per-column epilogue: normalize energy, softmax stats, write exp back into sK
    if (tid < 128) {
        const int n = tid;
        float S0 = 0.f, S1 = 0.f, S2 = 0.f, S3 = 0.f;
        #pragma unroll 8
        for (int j = 0; j < 128; j += 4) {
            S0 += sK[(j + 0) * 128 + n];
            S1 += sK[(j + 1) * 128 + n];
            S2 += sK[(j + 2) * 128 + n];
            S3 += sK[(j + 3) * 128 + n];
        }
        float S = (S0 + S1) + (S2 + S3);
        float sq = s_sq[n];
        float al = sq / (1e-9f + sq * S);

        float m0 = __int_as_float(0xff800000), m1 = m0, m2 = m0, m3 = m0;
        #pragma unroll 8
        for (int j = 0; j < 128; j += 4) {
            m0 = fmaxf(m0, al * sK[(j + 0) * 128 + n]);
            m1 = fmaxf(m1, al * sK[(j + 1) * 128 + n]);
            m2 = fmaxf(m2, al * sK[(j + 2) * 128 + n]);
            m3 = fmaxf(m3, al * sK[(j + 3) * 128 + n]);
        }
        float m = fmaxf(fmaxf(m0, m1), fmaxf(m2, m3));

        float d0 = 0.f, d1 = 0.f, d2 = 0.f, d3 = 0.f;
        #pragma unroll 8
        for (int j = 0; j < 128; j += 4) {
            float e0 = __expf(fmaf(al, sK[(j + 0) * 128 + n], -m));
            float e1 = __expf(fmaf(al, sK[(j + 1) * 128 + n], -m));
            float e2 = __expf(fmaf(al, sK[(j + 2) * 128 + n], -m));
            float e3 = __expf(fmaf(al, sK[(j + 3) * 128 + n], -m));
            sK[(j + 0) * 128 + n] = e0;
            sK[(j + 1) * 128 + n] = e1;
            sK[(j + 2) * 128 + n] = e2;
            sK[(j + 3) * 128 + n] = e3;
            d0 += e0; d1 += e1; d2 += e2; d3 += e3;
        }
        s_inv[n] = 1.0f / ((d0 + d1) + (d2 + d3));
    }
    __syncthreads();

    // Apply: out[j,n] = (exp_e[j,n] * inv[n]) * v[j,n] + feat[j,n]
    #pragma unroll
    for (int r = 0; r < 8; r++) {
        const int j = ty * 8 + r;
        float* og = out + base + (size_t)j * 16384 + tx * 8;
        const float* kr = sK + j * 128 + tx * 8;
        const float* fr = sF + j * 128 + tx * 8;
        #pragma unroll
        for (int c = 0; c < 4; c++) {
            float vlo = __uint_as_float((unsigned)(acc[r][c] & 0xffffffffu));
            float vhi = __uint_as_float((unsigned)(acc[r][c] >> 32));
            float i0 = s_inv[tx * 8 + 2 * c];
            float i1 = s_inv[tx * 8 + 2 * c + 1];
            float2 o;
            o.x = fmaf(kr[2 * c + 0] * i0, vlo, fr[2 * c + 0]);
            o.y = fmaf(kr[2 * c + 1] * i1, vhi, fr[2 * c + 1]);
            *(float2*)(og + 2 * c) = o;
        }
    }
}

extern "C" void kernel_launch(void* const* d_in, const int* in_sizes, int n_in,
                              void* d_out, int out_size) {
    const float* feat = (const float*)d_in[0];
    const float* pos  = (const float*)d_in[1];
    const float* Wq   = (const float*)d_in[2];
    const float* Wk   = (const float*)d_in[3];
    const float* Wv   = (const float*)d_in[4];
    float* out = (float*)d_out;

    wqsum_kernel<<<1, 128>>>(Wq);

    int smem_bytes = (3 * 16384 + CH * 128 + 256) * (int)sizeof(float);  // 205,824 B
    cudaFuncSetAttribute(csa_kernel, cudaFuncAttributeMaxDynamicSharedMemorySize,
                         smem_bytes);
    dim3 grid(16384 / 128, 16);
    csa_kernel<<<grid, 256, smem_bytes>>>(feat, pos, Wk, Wv, out);
}

// round 2
// speedup vs baseline: 1.3758x; 1.3758x over previous
#include <cuda_runtime.h>
#include <cstdint>

typedef unsigned long long ull;

__device__ float g_wqsum[128];
__device__ float g_WkT[128 * 128];  // WkT[c][o] = Wk[o][c]
__device__ float g_WvT[128 * 128];

// ---------------- prep kernels ----------------
__global__ void wqsum_kernel(const float* __restrict__ Wq) {
    int c = threadIdx.x;
    float s0 = 0.f, s1 = 0.f, s2 = 0.f, s3 = 0.f;
    #pragma unroll
    for (int o = 0; o < 128; o += 4) {
        s0 += Wq[(o + 0) * 128 + c];
        s1 += Wq[(o + 1) * 128 + c];
        s2 += Wq[(o + 2) * 128 + c];
        s3 += Wq[(o + 3) * 128 + c];
    }
    g_wqsum[c] = (s0 + s1) + (s2 + s3);
}

// Tiled transpose of Wk and Wv (blockIdx.z selects which) into device globals.
__global__ void transpose_kernel(const float* __restrict__ Wk,
                                 const float* __restrict__ Wv) {
    __shared__ float t[32][33];
    const float* src = blockIdx.z ? Wv : Wk;
    float* dst = blockIdx.z ? g_WvT : g_WkT;
    int x = blockIdx.x * 32 + threadIdx.x;
    #pragma unroll
    for (int i = threadIdx.y; i < 32; i += 8)
        t[i][threadIdx.x] = src[(blockIdx.y * 32 + i) * 128 + x];
    __syncthreads();
    int xo = blockIdx.y * 32 + threadIdx.x;
    #pragma unroll
    for (int i = threadIdx.y; i < 32; i += 8)
        dst[(blockIdx.x * 32 + i) * 128 + xo] = t[threadIdx.x][i];
}

// ---------------- f32x2 helpers ----------------
__device__ __forceinline__ void fma2(ull& d, ull a, ull b) {
    asm("fma.rn.f32x2 %0, %1, %2, %0;" : "+l"(d) : "l"(a), "l"(b));
}
__device__ __forceinline__ ull dup2(float w) {
    ull r;
    asm("mov.b64 %0, {%1, %1};" : "=l"(r) : "f"(w));
    return r;
}
__device__ __forceinline__ ull pack2(float a, float b) {
    ull r;
    asm("mov.b64 %0, {%1, %2};" : "=l"(r) : "f"(a), "f"(b));
    return r;
}
__device__ __forceinline__ float lo2(ull u) { return __uint_as_float((unsigned)u); }
__device__ __forceinline__ float hi2(ull u) { return __uint_as_float((unsigned)(u >> 32)); }

// ---------------- main kernel ----------------
// Tile: all 128 channels x 64 columns. 256 threads, 2 CTAs/SM.
// Thread tile: 8 j-rows (ty=tid>>4) x 4 n-cols (tx=tid&15), as 2 f32x2 pairs.
// smem (floats):
//   sP   [128][64]   @ 0       (8192)
//   sF   [128][64]   @ 8192    (8192)
//   sWk  [32][128]   @ 16384   (4096)
//   sWv  [32][128]   @ 20480   (4096)
//   sRed [16][68]    @ 24576   (1088)
//   s_sq [64]        @ 25664
//   s_al [64]        @ 25728
//   s_m  [64]        @ 25792
//   s_inv[64]        @ 25856
// total 25920 floats = 103,680 B -> 2 CTAs = 207,360 B / SM
__global__ void __launch_bounds__(256, 2)
csa_kernel(const float* __restrict__ feat, const float* __restrict__ pos,
           float* __restrict__ out) {
    extern __shared__ float sm[];
    float* sP = sm;
    float* sF = sm + 8192;
    float* sWk = sm + 16384;
    float* sWv = sm + 20480;
    float* sRed = sm + 24576;
    float* s_sq = sm + 25664;
    float* s_al = sm + 25728;
    float* s_m = sm + 25792;
    float* s_inv = sm + 25856;

    const int tid = threadIdx.x;
    const int tx = tid & 15;   // n group: cols tx*4 .. tx*4+3
    const int ty = tid >> 4;   // j group: rows ty*8 .. ty*8+7
    const int j0 = ty * 8;
    const size_t base = (size_t)blockIdx.y * (128u * 16384u) + (size_t)blockIdx.x * 64u;

    // Load pos/feat tiles: 128 rows x 16 float4 each.
    #pragma unroll
    for (int i = tid; i < 2048; i += 256) {
        int r = i >> 4, c4 = i & 15;
        ((float4*)sP)[i] = __ldg((const float4*)(pos + base + (size_t)r * 16384) + c4);
        ((float4*)sF)[i] = __ldg((const float4*)(feat + base + (size_t)r * 16384) + c4);
    }
    __syncthreads();

    // sq[n] = sum_c wqsum[c] * pos[c,n]   (conflict-free column reads)
    if (tid < 64) {
        float a0 = 0.f, a1 = 0.f, a2 = 0.f, a3 = 0.f;
        #pragma unroll
        for (int c = 0; c < 128; c += 4) {
            a0 = fmaf(g_wqsum[c + 0], sP[(c + 0) * 64 + tid], a0);
            a1 = fmaf(g_wqsum[c + 1], sP[(c + 1) * 64 + tid], a1);
            a2 = fmaf(g_wqsum[c + 2], sP[(c + 2) * 64 + tid], a2);
            a3 = fmaf(g_wqsum[c + 3], sP[(c + 3) * 64 + tid], a3);
        }
        s_sq[tid] = (a0 + a1) + (a2 + a3);
    }

    ull accK[8][2], accV[8][2];
    #pragma unroll
    for (int r = 0; r < 8; r++) {
        accK[r][0] = accK[r][1] = 0ull;
        accV[r][0] = accV[r][1] = 0ull;
    }

    // Fused dual GEMM: K = Wk*pos_tile, V = Wv*feat_tile, one pass over k.
    #pragma unroll 1
    for (int kc0 = 0; kc0 < 128; kc0 += 32) {
        // Stage pre-transposed weight chunks (straight coalesced copy).
        const float4* gk = (const float4*)(g_WkT + kc0 * 128);
        const float4* gv = (const float4*)(g_WvT + kc0 * 128);
        #pragma unroll
        for (int i = tid; i < 1024; i += 256) {
            ((float4*)sWk)[i] = __ldg(gk + i);
            ((float4*)sWv)[i] = __ldg(gv + i);
        }
        __syncthreads();
        #pragma unroll 8
        for (int kk = 0; kk < 32; kk++) {
            const ull* pr = (const ull*)(sP + (kc0 + kk) * 64 + tx * 4);
            ull p0 = pr[0], p1 = pr[1];
            const ull* fr = (const ull*)(sF + (kc0 + kk) * 64 + tx * 4);
            ull f0 = fr[0], f1 = fr[1];
            float wk[8], wv[8];
            *(float4*)(wk) = *(const float4*)(sWk + kk * 128 + j0);
            *(float4*)(wk + 4) = *(const float4*)(sWk + kk * 128 + j0 + 4);
            *(float4*)(wv) = *(const float4*)(sWv + kk * 128 + j0);
            *(float4*)(wv + 4) = *(const float4*)(sWv + kk * 128 + j0 + 4);
            #pragma unroll
            for (int r = 0; r < 8; r++) {
                ull wkp = dup2(wk[r]);
                fma2(accK[r][0], wkp, p0);
                fma2(accK[r][1], wkp, p1);
                ull wvp = dup2(wv[r]);
                fma2(accV[r][0], wvp, f0);
                fma2(accV[r][1], wvp, f1);
            }
        }
        __syncthreads();
    }

    float* myRed = sRed + ty * 68 + tx * 4;

    // ---- Phase A: S[n] = sum_j K[j,n]; al = sq/(1e-9 + sq*S) ----
    {
        float4 ps = {0.f, 0.f, 0.f, 0.f};
        #pragma unroll
        for (int r = 0; r < 8; r++) {
            ps.x += lo2(accK[r][0]);
            ps.y += hi2(accK[r][0]);
            ps.z += lo2(accK[r][1]);
            ps.w += hi2(accK[r][1]);
        }
        *(float4*)myRed = ps;
    }
    __syncthreads();
    if (tid < 64) {
        float S = 0.f;
        #pragma unroll
        for (int t = 0; t < 16; t++) S += sRed[t * 68 + tid];
        float sq = s_sq[tid];
        s_al[tid] = sq / (1e-9f + sq * S);
    }
    __syncthreads();
    float4 al4 = *(const float4*)(s_al + tx * 4);

    // ---- Phase B: m[n] = max_j al*K[j,n] ----
    {
        const float NEG = __int_as_float(0xff800000);
        float4 pm = {NEG, NEG, NEG, NEG};
        #pragma unroll
        for (int r = 0; r < 8; r++) {
            pm.x = fmaxf(pm.x, al4.x * lo2(accK[r][0]));
            pm.y = fmaxf(pm.y, al4.y * hi2(accK[r][0]));
            pm.z = fmaxf(pm.z, al4.z * lo2(accK[r][1]));
            pm.w = fmaxf(pm.w, al4.w * hi2(accK[r][1]));
        }
        *(float4*)myRed = pm;
    }
    __syncthreads();
    if (tid < 64) {
        float m = __int_as_float(0xff800000);
        #pragma unroll
        for (int t = 0; t < 16; t++) m = fmaxf(m, sRed[t * 68 + tid]);
        s_m[tid] = m;
    }
    __syncthreads();
    float4 m4 = *(const float4*)(s_m + tx * 4);

    // ---- Phase C: e = exp(al*K - m), denom; overwrite accK with e ----
    {
        float4 pd = {0.f, 0.f, 0.f, 0.f};
        #pragma unroll
        for (int r = 0; r < 8; r++) {
            float e0 = __expf(fmaf(al4.x, lo2(accK[r][0]), -m4.x));
            float e1 = __expf(fmaf(al4.y, hi2(accK[r][0]), -m4.y));
            float e2 = __expf(fmaf(al4.z, lo2(accK[r][1]), -m4.z));
            float e3 = __expf(fmaf(al4.w, hi2(accK[r][1]), -m4.w));
            accK[r][0] = pack2(e0, e1);
            accK[r][1] = pack2(e2, e3);
            pd.x += e0; pd.y += e1; pd.z += e2; pd.w += e3;
        }
        *(float4*)myRed = pd;
    }
    __syncthreads();
    if (tid < 64) {
        float d = 0.f;
        #pragma unroll
        for (int t = 0; t < 16; t++) d += sRed[t * 68 + tid];
        s_inv[tid] = 1.0f / d;
    }
    __syncthreads();
    float4 inv4 = *(const float4*)(s_inv + tx * 4);

    // ---- Apply: out = (e*inv)*V + feat ----
    #pragma unroll
    for (int r = 0; r < 8; r++) {
        float4 fv = *(const float4*)(sF + (j0 + r) * 64 + tx * 4);
        float4 o;
        o.x = fmaf(lo2(accK[r][0]) * inv4.x, lo2(accV[r][0]), fv.x);
        o.y = fmaf(hi2(accK[r][0]) * inv4.y, hi2(accV[r][0]), fv.y);
        o.z = fmaf(lo2(accK[r][1]) * inv4.z, lo2(accV[r][1]), fv.z);
        o.w = fmaf(hi2(accK[r][1]) * inv4.w, hi2(accV[r][1]), fv.w);
        *(float4*)(out + base + (size_t)(j0 + r) * 16384 + tx * 4) = o;
    }
}

extern "C" void kernel_launch(void* const* d_in, const int* in_sizes, int n_in,
                              void* d_out, int out_size) {
    const float* feat = (const float*)d_in[0];
    const float* pos  = (const float*)d_in[1];
    const float* Wq   = (const float*)d_in[2];
    const float* Wk   = (const float*)d_in[3];
    const float* Wv   = (const float*)d_in[4];
    float* out = (float*)d_out;

    wqsum_kernel<<<1, 128>>>(Wq);
    transpose_kernel<<<dim3(4, 4, 2), dim3(32, 8)>>>(Wk, Wv);

    int smem_bytes = 25920 * (int)sizeof(float);  // 103,680 B
    cudaFuncSetAttribute(csa_kernel, cudaFuncAttributeMaxDynamicSharedMemorySize,
                         smem_bytes);
    dim3 grid(16384 / 64, 16);
    csa_kernel<<<grid, 256, smem_bytes>>>(feat, pos, out);
}